// round 2
// baseline (speedup 1.0000x reference)
#include <cuda_runtime.h>

#define B   4
#define LQ  512
#define LK  512
#define E   128
#define D   256
#define TL  4            // l-rows per CTA
#define QT  64           // qq per stage tile
#define NT  (LQ / QT)    // 8 tiles
#define NTHR 256

// Scratch for projected q/k (allocation-free rule: __device__ globals)
__device__ float g_qproj[B * LQ * E];
__device__ float g_kproj[B * LK * E];

typedef unsigned long long ull;

__device__ __forceinline__ float tanha(float x) {
    float t;
    asm("tanh.approx.f32 %0, %1;" : "=f"(t) : "f"(x));
    return t;
}
__device__ __forceinline__ ull pk(float a, float b) {
    ull r; asm("mov.b64 %0, {%1, %2};" : "=l"(r) : "f"(a), "f"(b)); return r;
}
__device__ __forceinline__ float2 upk(ull v) {
    float2 r; asm("mov.b64 {%0, %1}, %2;" : "=f"(r.x), "=f"(r.y) : "l"(v)); return r;
}
__device__ __forceinline__ ull addx2(ull a, ull b) {
    ull r; asm("add.rn.f32x2 %0, %1, %2;" : "=l"(r) : "l"(a), "l"(b)); return r;
}
__device__ __forceinline__ ull fmax2(ull a, ull b, ull c) {
    ull r; asm("fma.rn.f32x2 %0, %1, %2, %3;" : "=l"(r) : "l"(a), "l"(b), "l"(c)); return r;
}

// ---------------------------------------------------------------------------
// Projection: out[r][e] = sum_d X[r][d] * W[d][e]
// blockIdx.y: 0 -> (query, Wc1, g_qproj), 1 -> (key, Wc2, g_kproj)
// ---------------------------------------------------------------------------
__global__ __launch_bounds__(128) void proj_kernel(
    const float* __restrict__ query, const float* __restrict__ key,
    const float* __restrict__ Wc1,   const float* __restrict__ Wc2)
{
    const float* X; const float* W; float* O;
    if (blockIdx.y == 0) { X = query; W = Wc1; O = g_qproj; }
    else                 { X = key;   W = Wc2; O = g_kproj; }

    const int row0 = blockIdx.x * 4;
    const int tid  = threadIdx.x;   // == e

    __shared__ float xs[4 * D];
    const float4* xv = (const float4*)(X + (size_t)row0 * D);
    #pragma unroll
    for (int i = tid; i < 4 * D / 4; i += 128)
        ((float4*)xs)[i] = xv[i];
    __syncthreads();

    float a0 = 0.f, a1 = 0.f, a2 = 0.f, a3 = 0.f;
    #pragma unroll 8
    for (int d = 0; d < D; d++) {
        float w = W[d * E + tid];
        a0 += xs[d      ] * w;
        a1 += xs[D  + d ] * w;
        a2 += xs[2*D + d] * w;
        a3 += xs[3*D + d] * w;
    }
    O[(size_t)(row0 + 0) * E + tid] = a0;
    O[(size_t)(row0 + 1) * E + tid] = a1;
    O[(size_t)(row0 + 2) * E + tid] = a2;
    O[(size_t)(row0 + 3) * E + tid] = a3;
}

// ---------------------------------------------------------------------------
// Fused scores + softmax + context. Grid (LK/TL, B) = 512 CTAs, 256 thr.
// Phase 1: lane = (l_sub = lane>>3, qq_off = lane&7); warp w owns qq block
//   w*8 .. w*8+7 within each 64-qq stage tile, for all 4 l-rows.
//   Padded smem rows (132 floats) make the 8-row q load and 4-row k load
//   land on disjoint bank groups -> 1 crossbar phase each (dedup/broadcast).
// Phase 2: per-warp softmax, warp w < TL owns row w.
// Phase 3: context GEMV, thread = (d4 = tid&63, l = tid>>6), f32x2 FMA.
// ---------------------------------------------------------------------------
__global__ __launch_bounds__(NTHR) void atten_kernel(
    const float* __restrict__ value, const float* __restrict__ vc,
    float* __restrict__ ctx_out, float* __restrict__ att_out)
{
    const int b    = blockIdx.y;
    const int l0   = blockIdx.x * TL;
    const int tid  = threadIdx.x;
    const int w    = tid >> 5;
    const int lane = tid & 31;

    __shared__ float ks[TL][132];      // 2.1 KB (padded rows: bank-shifted)
    __shared__ float vcs[E];           // 0.5 KB
    __shared__ float qs[QT][132];      // 33.8 KB (padded rows)
    __shared__ float ps[TL][LQ];       // 8 KB: scores, then probabilities

    for (int i = tid; i < TL * E; i += NTHR)
        ks[i >> 7][i & 127] = g_kproj[(size_t)(b * LK + l0 + (i >> 7)) * E + (i & 127)];
    if (tid < E) vcs[tid] = vc[tid];

    // ---- Phase 1: scores ----
    const int lrow = lane >> 3;              // 0..3
    const int qrow = w * 8 + (lane & 7);     // 0..63 within stage tile
    const float4* qbase = (const float4*)(g_qproj + (size_t)b * LQ * E);

    float4 pre[8];                           // register prefetch (one stage tile)
    #pragma unroll
    for (int j = 0; j < 8; j++) pre[j] = qbase[tid + j * NTHR];

    #pragma unroll 1
    for (int t = 0; t < NT; t++) {
        __syncthreads();                     // qs consumed (covers ks/vcs at t=0)
        #pragma unroll
        for (int j = 0; j < 8; j++) {
            int i = tid + j * NTHR;          // 0..2047
            *(float4*)&qs[i >> 5][(i & 31) * 4] = pre[j];
        }
        if (t + 1 < NT) {
            #pragma unroll
            for (int j = 0; j < 8; j++)
                pre[j] = qbase[(t + 1) * (QT * E / 4) + tid + j * NTHR];
        }
        __syncthreads();                     // qs ready (drains STS)

        const float4* qp = (const float4*)qs[qrow];
        const float4* kp = (const float4*)ks[lrow];
        const float4* vp = (const float4*)vcs;
        ull acc01 = pk(0.f, 0.f), acc23 = pk(0.f, 0.f);
        #pragma unroll 8
        for (int e4 = 0; e4 < E / 4; e4++) {
            float4 q = qp[e4];               // 128B unique, 1 phase
            float4 k = kp[e4];               // 64B unique, 1 phase
            float4 v = vp[e4];               // broadcast, 1 phase
            ull s01 = addx2(pk(q.x, q.y), pk(k.x, k.y));
            ull s23 = addx2(pk(q.z, q.w), pk(k.z, k.w));
            float2 t01 = upk(s01), t23 = upk(s23);
            t01.x = tanha(t01.x); t01.y = tanha(t01.y);
            t23.x = tanha(t23.x); t23.y = tanha(t23.y);
            acc01 = fmax2(pk(v.x, v.y), pk(t01.x, t01.y), acc01);
            acc23 = fmax2(pk(v.z, v.w), pk(t23.x, t23.y), acc23);
        }
        float2 a01 = upk(acc01), a23 = upk(acc23);
        ps[lrow][t * QT + qrow] = (a01.x + a01.y) + (a23.x + a23.y);
    }
    __syncthreads();

    // ---- Phase 2: softmax over qq (warp w < TL owns row w) ----
    if (w < TL) {
        float vals[LQ / 32];
        float m = -1e30f;
        #pragma unroll
        for (int k = 0; k < LQ / 32; k++) {
            vals[k] = ps[w][lane + 32 * k];
            m = fmaxf(m, vals[k]);
        }
        #pragma unroll
        for (int o = 16; o; o >>= 1) m = fmaxf(m, __shfl_xor_sync(0xffffffffu, m, o));
        float s = 0.f;
        #pragma unroll
        for (int k = 0; k < LQ / 32; k++) {
            vals[k] = __expf(vals[k] - m);
            s += vals[k];
        }
        #pragma unroll
        for (int o = 16; o; o >>= 1) s += __shfl_xor_sync(0xffffffffu, s, o);
        const float inv = __fdividef(1.f, s);

        float* arow = att_out + (size_t)(b * LK + l0 + w) * LQ;
        #pragma unroll
        for (int k = 0; k < LQ / 32; k++) {
            float p = vals[k] * inv;
            ps[w][lane + 32 * k] = p;        // reused by phase 3
            arow[lane + 32 * k]  = p;        // coalesced stores
        }
    }
    __syncthreads();

    // ---- Phase 3: context = atten @ value ----
    const int d4 = tid & 63;                 // float4 column
    const int lr = tid >> 6;                 // 0..3, one l-row per thread
    const float4* vbase = (const float4*)(value + (size_t)b * LQ * D);
    ull cxy = pk(0.f, 0.f), czw = pk(0.f, 0.f);
    #pragma unroll 4
    for (int qq = 0; qq < LQ; qq++) {
        float4 v = vbase[qq * (D / 4) + d4]; // 512B/warp, coalesced, L1-served
        float p  = ps[lr][qq];               // smem broadcast (l uniform per warp)
        ull p2 = pk(p, p);
        cxy = fmax2(p2, pk(v.x, v.y), cxy);
        czw = fmax2(p2, pk(v.z, v.w), czw);
    }
    float2 xy = upk(cxy), zw = upk(czw);
    float4 c = make_float4(xy.x, xy.y, zw.x, zw.y);
    ((float4*)ctx_out)[(size_t)(b * LK + l0 + lr) * (D / 4) + d4] = c;
}

// ---------------------------------------------------------------------------
extern "C" void kernel_launch(void* const* d_in, const int* in_sizes, int n_in,
                              void* d_out, int out_size)
{
    const float* query = (const float*)d_in[0];
    const float* key   = (const float*)d_in[1];
    const float* value = (const float*)d_in[2];
    const float* Wc1   = (const float*)d_in[3];
    const float* Wc2   = (const float*)d_in[4];
    const float* vc    = (const float*)d_in[5];

    float* ctx = (float*)d_out;                 // [B, LK, D]
    float* att = ctx + (size_t)B * LK * D;      // [B, LK, LQ]

    proj_kernel<<<dim3(B * LQ / 4, 2), 128>>>(query, key, Wc1, Wc2);
    atten_kernel<<<dim3(LK / TL, B), NTHR>>>(value, vc, ctx, att);
}

// round 4
// speedup vs baseline: 1.2746x; 1.2746x over previous
#include <cuda_runtime.h>
#include <cuda_fp16.h>

#define B   4
#define LQ  512
#define LK  512
#define E   128
#define D   256
#define TL  8            // l-rows per CTA
#define QT  32           // qq per stage tile
#define NT  (LQ / QT)    // 16 tiles
#define NTHR 256

// Scratch for projected q/k (allocation-free rule: __device__ globals)
__device__ float g_qproj[B * LQ * E];
__device__ float g_kproj[B * LK * E];

typedef unsigned long long ull;

__device__ __forceinline__ __half2 tanh_h2(__half2 x) {
    unsigned xu = *reinterpret_cast<unsigned*>(&x);
    unsigned r;
    asm("tanh.approx.f16x2 %0, %1;" : "=r"(r) : "r"(xu));
    return *reinterpret_cast<__half2*>(&r);
}
__device__ __forceinline__ ull pk(float a, float b) {
    ull r; asm("mov.b64 %0, {%1, %2};" : "=l"(r) : "f"(a), "f"(b)); return r;
}
__device__ __forceinline__ float2 upk(ull v) {
    float2 r; asm("mov.b64 {%0, %1}, %2;" : "=f"(r.x), "=f"(r.y) : "l"(v)); return r;
}
__device__ __forceinline__ ull fmax2(ull a, ull b, ull c) {
    ull r; asm("fma.rn.f32x2 %0, %1, %2, %3;" : "=l"(r) : "l"(a), "l"(b), "l"(c)); return r;
}
__device__ __forceinline__ void cpasync16(void* smem_dst, const void* gsrc) {
    unsigned s = (unsigned)__cvta_generic_to_shared(smem_dst);
    asm volatile("cp.async.cg.shared.global [%0], [%1], 16;" :: "r"(s), "l"(gsrc));
}

// ---------------------------------------------------------------------------
// Projection: out[r][e] = sum_d X[r][d] * W[d][e]
// ---------------------------------------------------------------------------
__global__ __launch_bounds__(128) void proj_kernel(
    const float* __restrict__ query, const float* __restrict__ key,
    const float* __restrict__ Wc1,   const float* __restrict__ Wc2)
{
    const float* X; const float* W; float* O;
    if (blockIdx.y == 0) { X = query; W = Wc1; O = g_qproj; }
    else                 { X = key;   W = Wc2; O = g_kproj; }

    const int row0 = blockIdx.x * 4;
    const int tid  = threadIdx.x;   // == e

    __shared__ float xs[4 * D];
    const float4* xv = (const float4*)(X + (size_t)row0 * D);
    #pragma unroll
    for (int i = tid; i < 4 * D / 4; i += 128)
        ((float4*)xs)[i] = xv[i];
    __syncthreads();

    float a0 = 0.f, a1 = 0.f, a2 = 0.f, a3 = 0.f;
    #pragma unroll 8
    for (int d = 0; d < D; d++) {
        float w = W[d * E + tid];
        a0 += xs[d      ] * w;
        a1 += xs[D  + d ] * w;
        a2 += xs[2*D + d] * w;
        a3 += xs[3*D + d] * w;
    }
    O[(size_t)(row0 + 0) * E + tid] = a0;
    O[(size_t)(row0 + 1) * E + tid] = a1;
    O[(size_t)(row0 + 2) * E + tid] = a2;
    O[(size_t)(row0 + 3) * E + tid] = a3;
}

// ---------------------------------------------------------------------------
// Fused scores + softmax + context. Grid (LK/TL=64, B) = 256 CTAs, 256 thr.
// Phase 1: lane = (lrow = lane>>2 in 0..7, qoff = lane&3); warp w owns
//   qq = w*4 + qoff within each 32-qq tile. q LDS: 4 rows x 16B (8-way dup,
//   1 phase); k LDS: 8 rows x 16B (4-way dup, 1 phase) -- padded 132-rows.
//   tanh via MUFU f16x2 (2 tanh/instr); f32 adds; HFMA2 chunk accumulation
//   flushed to f32 every 16 e. q tiles staged via cp.async double buffer.
// Phase 2: per-warp softmax, warp w owns row w.
// Phase 3: context GEMV with fma.rn.f32x2.
// ---------------------------------------------------------------------------
__global__ __launch_bounds__(NTHR) void atten_kernel(
    const float* __restrict__ value, const float* __restrict__ vc,
    float* __restrict__ ctx_out, float* __restrict__ att_out)
{
    const int b    = blockIdx.y;
    const int l0   = blockIdx.x * TL;
    const int tid  = threadIdx.x;
    const int w    = tid >> 5;
    const int lane = tid & 31;

    __shared__ float   ks[TL][132];      // 4.2 KB padded (rows bank-shifted)
    __shared__ __half2 vcs[E / 2];       // 256 B
    __shared__ float   qs[2][QT][132];   // 33.8 KB double buffer, padded
    __shared__ float   ps[TL][LQ];       // 16 KB scores -> probabilities

    for (int i = tid; i < TL * E; i += NTHR)
        ks[i >> 7][i & 127] = g_kproj[(size_t)(b * LK + l0 + (i >> 7)) * E + (i & 127)];
    if (tid < E / 2)
        vcs[tid] = __floats2half2_rn(vc[2 * tid], vc[2 * tid + 1]);

    const float4* qbase = (const float4*)(g_qproj + (size_t)b * LQ * E);

    // stage tile 0 into buffer 0
    #pragma unroll
    for (int j = 0; j < 4; j++) {
        int i = tid + j * NTHR;                          // 0..1023 float4s
        cpasync16(&qs[0][i >> 5][(i & 31) * 4], qbase + i);
    }
    asm volatile("cp.async.commit_group;");

    const int lrow = lane >> 2;              // 0..7
    const int qrow = w * 4 + (lane & 3);     // 0..31 within tile

    #pragma unroll 1
    for (int t = 0; t < NT; t++) {
        __syncthreads();   // everyone done reading buf[(t+1)&1] from iter t-1
        if (t + 1 < NT) {
            const float4* src = qbase + (t + 1) * (QT * E / 4);
            #pragma unroll
            for (int j = 0; j < 4; j++) {
                int i = tid + j * NTHR;
                cpasync16(&qs[(t + 1) & 1][i >> 5][(i & 31) * 4], src + i);
            }
            asm volatile("cp.async.commit_group;");
            asm volatile("cp.async.wait_group 1;");      // tile t has landed
        } else {
            asm volatile("cp.async.wait_group 0;");
        }
        __syncthreads();   // tile t visible to all warps

        const float4*  qp = (const float4*)qs[t & 1][qrow];
        const float4*  kp = (const float4*)ks[lrow];
        const uint2*   vp = (const uint2*)vcs;

        float facc = 0.f;
        #pragma unroll 4
        for (int c = 0; c < E / 16; c++) {               // 8 chunks of 16 e
            __half2 acc01 = __float2half2_rn(0.f);
            __half2 acc23 = __float2half2_rn(0.f);
            #pragma unroll
            for (int u = 0; u < 4; u++) {                // 4 e per sub-iter
                const int e4 = c * 4 + u;
                float4 q = qp[e4];                       // 1 phase (8-way dup)
                float4 k = kp[e4];                       // 1 phase (4-way dup)
                uint2  v = vp[e4];                       // broadcast
                __half2 h01 = __floats2half2_rn(q.x + k.x, q.y + k.y);
                __half2 h23 = __floats2half2_rn(q.z + k.z, q.w + k.w);
                __half2 t01 = tanh_h2(h01);
                __half2 t23 = tanh_h2(h23);
                __half2 v01 = *reinterpret_cast<__half2*>(&v.x);
                __half2 v23 = *reinterpret_cast<__half2*>(&v.y);
                acc01 = __hfma2(v01, t01, acc01);
                acc23 = __hfma2(v23, t23, acc23);
            }
            float2 f01 = __half22float2(acc01);
            float2 f23 = __half22float2(acc23);
            facc += (f01.x + f01.y) + (f23.x + f23.y);
        }
        ps[lrow][t * QT + qrow] = facc;
    }
    __syncthreads();

    // ---- Phase 2: softmax over qq (warp w owns row w) ----
    {
        float vals[LQ / 32];
        float m = -1e30f;
        #pragma unroll
        for (int k = 0; k < LQ / 32; k++) {
            vals[k] = ps[w][lane + 32 * k];
            m = fmaxf(m, vals[k]);
        }
        #pragma unroll
        for (int o = 16; o; o >>= 1) m = fmaxf(m, __shfl_xor_sync(0xffffffffu, m, o));
        float s = 0.f;
        #pragma unroll
        for (int k = 0; k < LQ / 32; k++) {
            vals[k] = __expf(vals[k] - m);
            s += vals[k];
        }
        #pragma unroll
        for (int o = 16; o; o >>= 1) s += __shfl_xor_sync(0xffffffffu, s, o);
        const float inv = __fdividef(1.f, s);

        float* arow = att_out + (size_t)(b * LK + l0 + w) * LQ;
        #pragma unroll
        for (int k = 0; k < LQ / 32; k++) {
            float p = vals[k] * inv;
            ps[w][lane + 32 * k] = p;        // reused by phase 3
            arow[lane + 32 * k]  = p;        // coalesced stores
        }
    }
    __syncthreads();

    // ---- Phase 3: context = atten @ value (f32x2 FMA) ----
    const int d4 = tid & 63;                 // float4 column
    const int lg = tid >> 6;                 // 0..3: rows lg and lg+4
    const float4* vbase = (const float4*)(value + (size_t)b * LQ * D);
    ull a0 = pk(0.f, 0.f), a1 = pk(0.f, 0.f);
    ull b0 = pk(0.f, 0.f), b1 = pk(0.f, 0.f);
    #pragma unroll 4
    for (int qq = 0; qq < LQ; qq++) {
        float4 v = vbase[qq * (D / 4) + d4]; // coalesced, L1-served after first warp
        ull vxy = pk(v.x, v.y), vzw = pk(v.z, v.w);
        float p0 = ps[lg][qq];               // smem broadcast
        float p1 = ps[lg + 4][qq];
        ull p02 = pk(p0, p0), p12 = pk(p1, p1);
        a0 = fmax2(p02, vxy, a0);
        a1 = fmax2(p02, vzw, a1);
        b0 = fmax2(p12, vxy, b0);
        b1 = fmax2(p12, vzw, b1);
    }
    float2 a0f = upk(a0), a1f = upk(a1), b0f = upk(b0), b1f = upk(b1);
    float4* cout = (float4*)ctx_out;
    cout[(size_t)(b * LK + l0 + lg    ) * (D / 4) + d4] =
        make_float4(a0f.x, a0f.y, a1f.x, a1f.y);
    cout[(size_t)(b * LK + l0 + lg + 4) * (D / 4) + d4] =
        make_float4(b0f.x, b0f.y, b1f.x, b1f.y);
}

// ---------------------------------------------------------------------------
extern "C" void kernel_launch(void* const* d_in, const int* in_sizes, int n_in,
                              void* d_out, int out_size)
{
    const float* query = (const float*)d_in[0];
    const float* key   = (const float*)d_in[1];
    const float* value = (const float*)d_in[2];
    const float* Wc1   = (const float*)d_in[3];
    const float* Wc2   = (const float*)d_in[4];
    const float* vc    = (const float*)d_in[5];

    float* ctx = (float*)d_out;                 // [B, LK, D]
    float* att = ctx + (size_t)B * LK * D;      // [B, LK, LQ]

    proj_kernel<<<dim3(B * LQ / 4, 2), 128>>>(query, key, Wc1, Wc2);
    atten_kernel<<<dim3(LK / TL, B), NTHR>>>(value, vc, ctx, att);
}